// round 2
// baseline (speedup 1.0000x reference)
#include <cuda_runtime.h>

#define SQ 4096
#define DM 1024
#define NH 16
#define HDIM 64

// Scratch (allocation-free): head-major Q/K/V [H][S][64] and attention output [S][D]
__device__ float g_q[SQ * DM];
__device__ float g_k[SQ * DM];
__device__ float g_v[SQ * DM];
__device__ float g_ao[SQ * DM];

// ---------------------------------------------------------------------------
// Fused QKV projection: C = x[S,D] @ W[N,D]^T, per blockIdx.z in {Wq,Wk,Wv}.
// Writes head-major: g_{q,k,v}[head][s][hd], head = col_tile (64 == HD).
// 64x64 tile, Ktile=16, 256 threads, 4x4 microtile.
// ---------------------------------------------------------------------------
__global__ __launch_bounds__(256) void qkv_gemm(
    const float* __restrict__ x,
    const float* __restrict__ Wq,
    const float* __restrict__ Wk,
    const float* __restrict__ Wv)
{
    __shared__ float As[16][64];   // [kk][m]
    __shared__ float Bs[16][64];   // [kk][n]
    const float* Bmat = (blockIdx.z == 0) ? Wq : ((blockIdx.z == 1) ? Wk : Wv);
    float* Cbuf = (blockIdx.z == 0) ? g_q : ((blockIdx.z == 1) ? g_k : g_v);

    const int tid = threadIdx.x;
    const int ty = tid >> 4, tx = tid & 15;
    const int lr = tid >> 2, lc = (tid & 3) << 2;
    const int row0 = blockIdx.x << 6;
    const int col0 = blockIdx.y << 6;

    const float* Ap = x + (row0 + lr) * DM + lc;
    const float* Bp = Bmat + (col0 + lr) * DM + lc;

    float acc[4][4] = {};

    for (int kt = 0; kt < DM; kt += 16) {
        float4 av = *(const float4*)(Ap + kt);
        float4 bv = *(const float4*)(Bp + kt);
        As[lc + 0][lr] = av.x; As[lc + 1][lr] = av.y;
        As[lc + 2][lr] = av.z; As[lc + 3][lr] = av.w;
        Bs[lc + 0][lr] = bv.x; Bs[lc + 1][lr] = bv.y;
        Bs[lc + 2][lr] = bv.z; Bs[lc + 3][lr] = bv.w;
        __syncthreads();
#pragma unroll
        for (int kk = 0; kk < 16; kk++) {
            float4 a = *(const float4*)&As[kk][ty << 2];
            float4 b = *(const float4*)&Bs[kk][tx << 2];
            float aa[4] = {a.x, a.y, a.z, a.w};
            float bb[4] = {b.x, b.y, b.z, b.w};
#pragma unroll
            for (int i = 0; i < 4; i++)
#pragma unroll
                for (int j = 0; j < 4; j++)
                    acc[i][j] = fmaf(aa[i], bb[j], acc[i][j]);
        }
        __syncthreads();
    }

    // head-major store: head = blockIdx.y (col tile == head since HD == 64)
    float* op = Cbuf + (size_t)blockIdx.y * SQ * HDIM;
#pragma unroll
    for (int i = 0; i < 4; i++) {
        int s = row0 + (ty << 2) + i;
        float4 o4 = make_float4(acc[i][0], acc[i][1], acc[i][2], acc[i][3]);
        *(float4*)&op[s * HDIM + (tx << 2)] = o4;
    }
}

// ---------------------------------------------------------------------------
// Causal flash attention. One CTA per (query-tile of 64, head).
// 256 threads, 4x4 microtiles for both the 64x64 score tile and 64x64 O tile.
// Online softmax with per-row (m, l) carried in registers, row stats reduced
// across the 16 lanes that share a row via __shfl_xor.
// Dynamic smem: Qs[64][64] + Ks[64][64] (k-major) + Vs[64][64] + Ps[64][65].
// NOTE: full 64x64 tile loads need each thread to load 16 elements
// (4 float4 chunks, c = 0,16,32,48) -- this was the round-1 correctness bug.
// ---------------------------------------------------------------------------
__global__ __launch_bounds__(256) void attn_kernel()
{
    extern __shared__ float sm[];
    float* Qs = sm;            // Qs[kk*64 + m]
    float* Ks = sm + 4096;     // Ks[kk*64 + n]
    float* Vs = sm + 8192;     // Vs[n*64 + hd]
    float* Ps = sm + 12288;    // Ps[n*65 + m]  (padded)

    const int tid = threadIdx.x;
    const int ty = tid >> 4, tx = tid & 15;
    const int lr = tid >> 2, lc = (tid & 3) << 2;
    const int h = blockIdx.y, qt = blockIdx.x;

    const float* Qh = g_q + (size_t)h * SQ * HDIM;
    const float* Kh = g_k + (size_t)h * SQ * HDIM;
    const float* Vh = g_v + (size_t)h * SQ * HDIM;

    // load Q tile once (transposed into k-major), full 64 columns per row
#pragma unroll
    for (int c = 0; c < HDIM; c += 16) {
        float4 qv = *(const float4*)(Qh + (qt * 64 + lr) * HDIM + c + lc);
        Qs[(c + lc + 0) * 64 + lr] = qv.x;
        Qs[(c + lc + 1) * 64 + lr] = qv.y;
        Qs[(c + lc + 2) * 64 + lr] = qv.z;
        Qs[(c + lc + 3) * 64 + lr] = qv.w;
    }

    float oacc[4][4] = {};
    float mrow[4] = {-1e30f, -1e30f, -1e30f, -1e30f};
    float lsum[4] = {0.f, 0.f, 0.f, 0.f};
    const float scale = 0.125f;  // 1/sqrt(64)

    for (int jt = 0; jt <= qt; jt++) {
        __syncthreads();  // prev-iter PV readers done before K/V overwrite
#pragma unroll
        for (int c = 0; c < HDIM; c += 16) {
            float4 kv = *(const float4*)(Kh + (jt * 64 + lr) * HDIM + c + lc);
            Ks[(c + lc + 0) * 64 + lr] = kv.x;
            Ks[(c + lc + 1) * 64 + lr] = kv.y;
            Ks[(c + lc + 2) * 64 + lr] = kv.z;
            Ks[(c + lc + 3) * 64 + lr] = kv.w;
            float4 vv = *(const float4*)(Vh + (jt * 64 + lr) * HDIM + c + lc);
            *(float4*)&Vs[lr * 64 + c + lc] = vv;
        }
        __syncthreads();

        // S = Q @ K^T
        float s[4][4] = {};
#pragma unroll 16
        for (int kk = 0; kk < HDIM; kk++) {
            float4 a = *(const float4*)&Qs[kk * 64 + (ty << 2)];
            float4 b = *(const float4*)&Ks[kk * 64 + (tx << 2)];
            float aa[4] = {a.x, a.y, a.z, a.w};
            float bb[4] = {b.x, b.y, b.z, b.w};
#pragma unroll
            for (int i = 0; i < 4; i++)
#pragma unroll
                for (int j = 0; j < 4; j++)
                    s[i][j] = fmaf(aa[i], bb[j], s[i][j]);
        }

        // scale + causal mask (only the diagonal tile needs masking)
        if (jt == qt) {
#pragma unroll
            for (int i = 0; i < 4; i++)
#pragma unroll
                for (int j = 0; j < 4; j++) {
                    int m = (ty << 2) + i, n = (tx << 2) + j;
                    s[i][j] = (n > m) ? -1e30f : s[i][j] * scale;
                }
        } else {
#pragma unroll
            for (int i = 0; i < 4; i++)
#pragma unroll
                for (int j = 0; j < 4; j++) s[i][j] *= scale;
        }

        // online softmax update (row stats across the 16 lanes sharing a row)
#pragma unroll
        for (int i = 0; i < 4; i++) {
            float rm = fmaxf(fmaxf(s[i][0], s[i][1]), fmaxf(s[i][2], s[i][3]));
#pragma unroll
            for (int off = 1; off < 16; off <<= 1)
                rm = fmaxf(rm, __shfl_xor_sync(0xffffffffu, rm, off));
            float mnew = fmaxf(mrow[i], rm);
            float alpha = __expf(mrow[i] - mnew);
            mrow[i] = mnew;
            float rs = 0.f;
#pragma unroll
            for (int j = 0; j < 4; j++) {
                float p = __expf(s[i][j] - mnew);
                s[i][j] = p;
                rs += p;
            }
#pragma unroll
            for (int off = 1; off < 16; off <<= 1)
                rs += __shfl_xor_sync(0xffffffffu, rs, off);
            lsum[i] = lsum[i] * alpha + rs;
#pragma unroll
            for (int j = 0; j < 4; j++) oacc[i][j] *= alpha;
        }

        // P -> smem (transposed, padded stride 65)
#pragma unroll
        for (int i = 0; i < 4; i++)
#pragma unroll
            for (int j = 0; j < 4; j++)
                Ps[((tx << 2) + j) * 65 + (ty << 2) + i] = s[i][j];
        __syncthreads();

        // O += P @ V
#pragma unroll 16
        for (int n = 0; n < 64; n++) {
            float4 b = *(const float4*)&Vs[n * 64 + (tx << 2)];
            float bb[4] = {b.x, b.y, b.z, b.w};
            float pa[4];
#pragma unroll
            for (int i = 0; i < 4; i++) pa[i] = Ps[n * 65 + (ty << 2) + i];
#pragma unroll
            for (int i = 0; i < 4; i++)
#pragma unroll
                for (int j = 0; j < 4; j++)
                    oacc[i][j] = fmaf(pa[i], bb[j], oacc[i][j]);
        }
    }

    // epilogue: normalize and write [s][d] layout for the output projection
#pragma unroll
    for (int i = 0; i < 4; i++) {
        float inv = 1.f / lsum[i];
        int srow = qt * 64 + (ty << 2) + i;
        float4 o4 = make_float4(oacc[i][0] * inv, oacc[i][1] * inv,
                                oacc[i][2] * inv, oacc[i][3] * inv);
        *(float4*)&g_ao[(size_t)srow * DM + h * HDIM + (tx << 2)] = o4;
    }
}

// ---------------------------------------------------------------------------
// Output projection: out = attn_out[S,D] @ Wo[D,D]^T
// ---------------------------------------------------------------------------
__global__ __launch_bounds__(256) void out_gemm(
    const float* __restrict__ Wo, float* __restrict__ out)
{
    __shared__ float As[16][64];
    __shared__ float Bs[16][64];

    const int tid = threadIdx.x;
    const int ty = tid >> 4, tx = tid & 15;
    const int lr = tid >> 2, lc = (tid & 3) << 2;
    const int row0 = blockIdx.x << 6;
    const int col0 = blockIdx.y << 6;

    const float* Ap = g_ao + (row0 + lr) * DM + lc;
    const float* Bp = Wo + (col0 + lr) * DM + lc;

    float acc[4][4] = {};

    for (int kt = 0; kt < DM; kt += 16) {
        float4 av = *(const float4*)(Ap + kt);
        float4 bv = *(const float4*)(Bp + kt);
        As[lc + 0][lr] = av.x; As[lc + 1][lr] = av.y;
        As[lc + 2][lr] = av.z; As[lc + 3][lr] = av.w;
        Bs[lc + 0][lr] = bv.x; Bs[lc + 1][lr] = bv.y;
        Bs[lc + 2][lr] = bv.z; Bs[lc + 3][lr] = bv.w;
        __syncthreads();
#pragma unroll
        for (int kk = 0; kk < 16; kk++) {
            float4 a = *(const float4*)&As[kk][ty << 2];
            float4 b = *(const float4*)&Bs[kk][tx << 2];
            float aa[4] = {a.x, a.y, a.z, a.w};
            float bb[4] = {b.x, b.y, b.z, b.w};
#pragma unroll
            for (int i = 0; i < 4; i++)
#pragma unroll
                for (int j = 0; j < 4; j++)
                    acc[i][j] = fmaf(aa[i], bb[j], acc[i][j]);
        }
        __syncthreads();
    }

#pragma unroll
    for (int i = 0; i < 4; i++) {
        int r = row0 + (ty << 2) + i;
        float4 o4 = make_float4(acc[i][0], acc[i][1], acc[i][2], acc[i][3]);
        *(float4*)&out[(size_t)r * DM + col0 + (tx << 2)] = o4;
    }
}

// ---------------------------------------------------------------------------
// inputs (metadata order): 0=x [1,4096,1024] f32, 1=mask (ignored; causal is
// structural), 2=Wq, 3=Wk, 4=Wv, 5=Wo (all [1024,1024] f32). out: [1,4096,1024] f32.
// ---------------------------------------------------------------------------
extern "C" void kernel_launch(void* const* d_in, const int* in_sizes, int n_in,
                              void* d_out, int out_size)
{
    const float* x  = (const float*)d_in[0];
    const float* Wq = (const float*)d_in[2];
    const float* Wk = (const float*)d_in[3];
    const float* Wv = (const float*)d_in[4];
    const float* Wo = (const float*)d_in[5];
    float* out = (float*)d_out;

    // 64.25 KB dynamic smem for the attention kernel (above the 48 KB default)
    cudaFuncSetAttribute(attn_kernel,
                         cudaFuncAttributeMaxDynamicSharedMemorySize, 65792);

    dim3 gq(SQ / 64, DM / 64, 3);
    qkv_gemm<<<gq, 256>>>(x, Wq, Wk, Wv);

    dim3 ga(SQ / 64, NH);
    attn_kernel<<<ga, 256, 65792>>>();

    dim3 go(SQ / 64, DM / 64);
    out_gemm<<<go, 256>>>(Wo, out);
}

// round 4
// speedup vs baseline: 3.6954x; 3.6954x over previous
#include <cuda_runtime.h>

#define SQ 4096
#define DM 1024
#define NH 16
#define HDIM 64

// Scratch: head-major Q/K/V [H][S][64] and attention output [S][D].
// NOTE: referenced ONLY from device code (host-side symbol address is invalid).
__device__ float g_q[SQ * DM];
__device__ float g_k[SQ * DM];
__device__ float g_v[SQ * DM];
__device__ float g_ao[SQ * DM];

__device__ __forceinline__ unsigned f2tf(float f) {
    unsigned u;
    asm("cvt.rna.tf32.f32 %0, %1;" : "=r"(u) : "f"(f));
    return u;
}

__device__ __forceinline__ void mma_tf32(float* c, const unsigned* a, const unsigned* b) {
    asm("mma.sync.aligned.m16n8k8.row.col.f32.tf32.tf32.f32 "
        "{%0,%1,%2,%3},{%4,%5,%6,%7},{%8,%9},{%0,%1,%2,%3};"
        : "+f"(c[0]), "+f"(c[1]), "+f"(c[2]), "+f"(c[3])
        : "r"(a[0]), "r"(a[1]), "r"(a[2]), "r"(a[3]), "r"(b[0]), "r"(b[1]));
}

// ---------------------------------------------------------------------------
// Projection GEMM: C = A[S,DM] @ W[N,DM]^T, tf32 tensor cores.
// CTA tile 128x128, Ktile 32, 8 warps in 2(m) x 4(n), warp tile 64x32.
// Smem [row][36] padding: stride%32==4 -> conflict-free fragment LDS.
// mode 0: A=A_ext (x), W per blockIdx.z, C = g_q/g_k/g_v head-major [head][s][64].
// mode 1: A=g_ao, W=W0 (Wo), C = C_ext (d_out) row-major [s][DM].
// ---------------------------------------------------------------------------
__global__ __launch_bounds__(256) void proj_gemm(
    const float* __restrict__ A_ext,
    const float* __restrict__ W0, const float* __restrict__ W1,
    const float* __restrict__ W2,
    float* __restrict__ C_ext, int mode)
{
    __shared__ unsigned As[128 * 36];
    __shared__ unsigned Bs[128 * 36];

    const float* A;
    const float* W;
    float* C;
    if (mode == 0) {
        A = A_ext;
        W = (blockIdx.z == 0) ? W0 : ((blockIdx.z == 1) ? W1 : W2);
        C = (blockIdx.z == 0) ? g_q : ((blockIdx.z == 1) ? g_k : g_v);
    } else {
        A = g_ao;
        W = W0;
        C = C_ext;
    }

    const int tid = threadIdx.x;
    const int wid = tid >> 5, lane = tid & 31;
    const int g = lane >> 2, q = lane & 3;
    const int wm = (wid >> 2) * 64;      // 0 or 64
    const int wn = (wid & 3) * 32;       // 0,32,64,96
    const int row0 = blockIdx.x << 7;
    const int col0 = blockIdx.y << 7;
    const int lr = tid >> 3;             // 0..31
    const int lc = (tid & 7) << 2;       // 0..28

    float acc[4][4][4];
#pragma unroll
    for (int i = 0; i < 4; i++)
#pragma unroll
        for (int j = 0; j < 4; j++)
#pragma unroll
            for (int r = 0; r < 4; r++) acc[i][j][r] = 0.f;

    for (int kt = 0; kt < DM; kt += 32) {
#pragma unroll
        for (int c = 0; c < 4; c++) {
            int r = c * 32 + lr;
            float4 av = *(const float4*)(A + (size_t)(row0 + r) * DM + kt + lc);
            float4 bv = *(const float4*)(W + (size_t)(col0 + r) * DM + kt + lc);
            uint4 au = make_uint4(f2tf(av.x), f2tf(av.y), f2tf(av.z), f2tf(av.w));
            uint4 bu = make_uint4(f2tf(bv.x), f2tf(bv.y), f2tf(bv.z), f2tf(bv.w));
            *(uint4*)&As[r * 36 + lc] = au;
            *(uint4*)&Bs[r * 36 + lc] = bu;
        }
        __syncthreads();
#pragma unroll
        for (int ks = 0; ks < 4; ks++) {
            unsigned af[4][4], bf[4][2];
#pragma unroll
            for (int mt = 0; mt < 4; mt++) {
                int base = (wm + mt * 16 + g) * 36 + ks * 8 + q;
                af[mt][0] = As[base];
                af[mt][1] = As[base + 8 * 36];
                af[mt][2] = As[base + 4];
                af[mt][3] = As[base + 8 * 36 + 4];
            }
#pragma unroll
            for (int nt = 0; nt < 4; nt++) {
                int base = (wn + nt * 8 + g) * 36 + ks * 8 + q;
                bf[nt][0] = Bs[base];
                bf[nt][1] = Bs[base + 4];
            }
#pragma unroll
            for (int mt = 0; mt < 4; mt++)
#pragma unroll
                for (int nt = 0; nt < 4; nt++)
                    mma_tf32(acc[mt][nt], af[mt], bf[nt]);
        }
        __syncthreads();
    }

#pragma unroll
    for (int mt = 0; mt < 4; mt++)
#pragma unroll
        for (int nt = 0; nt < 4; nt++) {
            int row = row0 + wm + mt * 16 + g;
            int col = col0 + wn + nt * 8 + 2 * q;
            if (mode == 0) {
                float* p0 = C + (size_t)(col >> 6) * SQ * HDIM + (size_t)row * HDIM + (col & 63);
                float* p1 = C + (size_t)(col >> 6) * SQ * HDIM + (size_t)(row + 8) * HDIM + (col & 63);
                p0[0] = acc[mt][nt][0]; p0[1] = acc[mt][nt][1];
                p1[0] = acc[mt][nt][2]; p1[1] = acc[mt][nt][3];
            } else {
                float* p0 = C + (size_t)row * DM + col;
                float* p1 = C + (size_t)(row + 8) * DM + col;
                p0[0] = acc[mt][nt][0]; p0[1] = acc[mt][nt][1];
                p1[0] = acc[mt][nt][2]; p1[1] = acc[mt][nt][3];
            }
        }
}

// ---------------------------------------------------------------------------
// Causal flash attention, tf32 tensor cores.
// 128 threads = 4 warps; warp owns 16 score rows x full 64 cols (nt=0..7).
// Q fragments preloaded to registers (Q smem reused as P smem; P never
// crosses warps, so only __syncwarp between P store and PV mma).
// Smem: Qs/Ps [64][68], Ks [64][68], Vt [64][72] (k-major V).
// ---------------------------------------------------------------------------
__global__ __launch_bounds__(128) void attn_kernel()
{
    extern __shared__ unsigned sm[];
    unsigned* Qs = sm;                   // [64][68], later reused as Ps
    unsigned* Ks = sm + 64 * 68;         // [64][68]
    unsigned* Vt = sm + 2 * 64 * 68;     // [64][72] : Vt[k*72 + hd]
    unsigned* Ps = Qs;

    const int tid = threadIdx.x;
    const int wid = tid >> 5, lane = tid & 31;
    const int g = lane >> 2, q = lane & 3;
    const int wm = wid * 16;
    const int qt = 63 - blockIdx.x;      // reversed: heavy tiles first
    const int h = blockIdx.y;
    const int lr = tid >> 4;             // 0..7
    const int lc = (tid & 15) << 2;      // 0..60

    const float* Qh = g_q + (size_t)h * SQ * HDIM;
    const float* Kh = g_k + (size_t)h * SQ * HDIM;
    const float* Vh = g_v + (size_t)h * SQ * HDIM;

    // Q tile -> smem (tf32)
#pragma unroll
    for (int c = 0; c < 8; c++) {
        int r = c * 8 + lr;
        float4 v = *(const float4*)(Qh + (size_t)(qt * 64 + r) * HDIM + lc);
        *(uint4*)&Qs[r * 68 + lc] = make_uint4(f2tf(v.x), f2tf(v.y), f2tf(v.z), f2tf(v.w));
    }
    __syncthreads();

    // Q fragments -> registers (invariant across jt); own-warp rows only
    unsigned qf[8][4];
#pragma unroll
    for (int ks = 0; ks < 8; ks++) {
        int base = (wm + g) * 68 + ks * 8 + q;
        qf[ks][0] = Qs[base];
        qf[ks][1] = Qs[base + 8 * 68];
        qf[ks][2] = Qs[base + 4];
        qf[ks][3] = Qs[base + 8 * 68 + 4];
    }

    float oacc[8][4];
#pragma unroll
    for (int nt = 0; nt < 8; nt++)
#pragma unroll
        for (int r = 0; r < 4; r++) oacc[nt][r] = 0.f;
    float m0 = -1e30f, m1 = -1e30f, l0 = 0.f, l1 = 0.f;
    const float scale = 0.125f;

    for (int jt = 0; jt <= qt; jt++) {
        __syncthreads();  // all warps done with prev Ks/Vt before overwrite
#pragma unroll
        for (int c = 0; c < 8; c++) {
            int r = c * 8 + lr;
            float4 kv = *(const float4*)(Kh + (size_t)(jt * 64 + r) * HDIM + lc);
            *(uint4*)&Ks[r * 68 + lc] = make_uint4(f2tf(kv.x), f2tf(kv.y), f2tf(kv.z), f2tf(kv.w));
            float4 vv = *(const float4*)(Vh + (size_t)(jt * 64 + r) * HDIM + lc);
            *(uint4*)&Vt[r * 72 + lc] = make_uint4(f2tf(vv.x), f2tf(vv.y), f2tf(vv.z), f2tf(vv.w));
        }
        __syncthreads();

        // S = Q @ K^T  (warp: 16 x 64)
        float sa[8][4];
#pragma unroll
        for (int nt = 0; nt < 8; nt++)
#pragma unroll
            for (int r = 0; r < 4; r++) sa[nt][r] = 0.f;
#pragma unroll
        for (int ks = 0; ks < 8; ks++) {
            unsigned kf[8][2];
#pragma unroll
            for (int nt = 0; nt < 8; nt++) {
                int base = (nt * 8 + g) * 68 + ks * 8 + q;
                kf[nt][0] = Ks[base];
                kf[nt][1] = Ks[base + 4];
            }
#pragma unroll
            for (int nt = 0; nt < 8; nt++)
                mma_tf32(sa[nt], qf[ks], kf[nt]);
        }

        // scale + causal mask (diag tile only)
        if (jt == qt) {
            int r0 = wm + g, r1 = wm + g + 8;
#pragma unroll
            for (int nt = 0; nt < 8; nt++) {
                int c0 = nt * 8 + 2 * q, c1 = c0 + 1;
                sa[nt][0] = (c0 > r0) ? -1e30f : sa[nt][0] * scale;
                sa[nt][1] = (c1 > r0) ? -1e30f : sa[nt][1] * scale;
                sa[nt][2] = (c0 > r1) ? -1e30f : sa[nt][2] * scale;
                sa[nt][3] = (c1 > r1) ? -1e30f : sa[nt][3] * scale;
            }
        } else {
#pragma unroll
            for (int nt = 0; nt < 8; nt++)
#pragma unroll
                for (int r = 0; r < 4; r++) sa[nt][r] *= scale;
        }

        // online softmax: rows r0 (c0,c1) and r1 (c2,c3); quad shuffles
        float rm0 = -1e30f, rm1 = -1e30f;
#pragma unroll
        for (int nt = 0; nt < 8; nt++) {
            rm0 = fmaxf(rm0, fmaxf(sa[nt][0], sa[nt][1]));
            rm1 = fmaxf(rm1, fmaxf(sa[nt][2], sa[nt][3]));
        }
#pragma unroll
        for (int off = 1; off < 4; off <<= 1) {
            rm0 = fmaxf(rm0, __shfl_xor_sync(0xffffffffu, rm0, off));
            rm1 = fmaxf(rm1, __shfl_xor_sync(0xffffffffu, rm1, off));
        }
        float mn0 = fmaxf(m0, rm0), mn1 = fmaxf(m1, rm1);
        float al0 = __expf(m0 - mn0), al1 = __expf(m1 - mn1);
        m0 = mn0; m1 = mn1;
        float rs0 = 0.f, rs1 = 0.f;
#pragma unroll
        for (int nt = 0; nt < 8; nt++) {
            sa[nt][0] = __expf(sa[nt][0] - mn0);
            sa[nt][1] = __expf(sa[nt][1] - mn0);
            sa[nt][2] = __expf(sa[nt][2] - mn1);
            sa[nt][3] = __expf(sa[nt][3] - mn1);
            rs0 += sa[nt][0] + sa[nt][1];
            rs1 += sa[nt][2] + sa[nt][3];
        }
#pragma unroll
        for (int off = 1; off < 4; off <<= 1) {
            rs0 += __shfl_xor_sync(0xffffffffu, rs0, off);
            rs1 += __shfl_xor_sync(0xffffffffu, rs1, off);
        }
        l0 = l0 * al0 + rs0;
        l1 = l1 * al1 + rs1;
#pragma unroll
        for (int nt = 0; nt < 8; nt++) {
            oacc[nt][0] *= al0; oacc[nt][1] *= al0;
            oacc[nt][2] *= al1; oacc[nt][3] *= al1;
        }

        // P -> smem (tf32), own-warp rows only
#pragma unroll
        for (int nt = 0; nt < 8; nt++) {
            int a0 = (wm + g) * 68 + nt * 8 + 2 * q;
            int a1 = (wm + g + 8) * 68 + nt * 8 + 2 * q;
            Ps[a0] = f2tf(sa[nt][0]); Ps[a0 + 1] = f2tf(sa[nt][1]);
            Ps[a1] = f2tf(sa[nt][2]); Ps[a1 + 1] = f2tf(sa[nt][3]);
        }
        __syncwarp();

        // O += P @ V  (warp: 16 x 64)
#pragma unroll
        for (int ks = 0; ks < 8; ks++) {
            unsigned pf[4];
            int base = (wm + g) * 68 + ks * 8 + q;
            pf[0] = Ps[base];
            pf[1] = Ps[base + 8 * 68];
            pf[2] = Ps[base + 4];
            pf[3] = Ps[base + 8 * 68 + 4];
#pragma unroll
            for (int nt = 0; nt < 8; nt++) {
                unsigned vb[2];
                int vbase = (ks * 8 + q) * 72 + nt * 8 + g;
                vb[0] = Vt[vbase];
                vb[1] = Vt[vbase + 4 * 72];
                mma_tf32(oacc[nt], pf, vb);
            }
        }
    }

    // epilogue: normalize, write [s][d] for the output projection
    float inv0 = 1.f / l0, inv1 = 1.f / l1;
#pragma unroll
    for (int nt = 0; nt < 8; nt++) {
        int row = qt * 64 + wm + g;
        int col = h * HDIM + nt * 8 + 2 * q;
        float* p0 = g_ao + (size_t)row * DM + col;
        float* p1 = g_ao + (size_t)(row + 8) * DM + col;
        p0[0] = oacc[nt][0] * inv0; p0[1] = oacc[nt][1] * inv0;
        p1[0] = oacc[nt][2] * inv1; p1[1] = oacc[nt][3] * inv1;
    }
}

// ---------------------------------------------------------------------------
// inputs: 0=x, 1=mask (ignored; causal structural), 2=Wq, 3=Wk, 4=Wv, 5=Wo
// ---------------------------------------------------------------------------
extern "C" void kernel_launch(void* const* d_in, const int* in_sizes, int n_in,
                              void* d_out, int out_size)
{
    const float* x  = (const float*)d_in[0];
    const float* Wq = (const float*)d_in[2];
    const float* Wk = (const float*)d_in[3];
    const float* Wv = (const float*)d_in[4];
    const float* Wo = (const float*)d_in[5];
    float* out = (float*)d_out;

    cudaFuncSetAttribute(attn_kernel,
                         cudaFuncAttributeMaxDynamicSharedMemorySize, 53248);

    dim3 gq(SQ / 128, DM / 128, 3);
    proj_gemm<<<gq, 256>>>(x, Wq, Wk, Wv, nullptr, 0);

    dim3 ga(SQ / 64, NH);
    attn_kernel<<<ga, 128, 53248>>>();

    dim3 go(SQ / 128, DM / 128, 1);
    proj_gemm<<<go, 256>>>(nullptr, Wo, nullptr, nullptr, out, 1);
}

// round 5
// speedup vs baseline: 3.6967x; 1.0004x over previous
#include <cuda_runtime.h>

#define SQ 4096
#define DM 1024
#define NH 16
#define HDIM 64

// Scratch: head-major Q/K/V [H][S][64] and attention output [S][D].
// Referenced ONLY from device code (host-side symbol address is invalid).
__device__ float g_q[SQ * DM];
__device__ float g_k[SQ * DM];
__device__ float g_v[SQ * DM];
__device__ float g_ao[SQ * DM];

__device__ __forceinline__ unsigned f2tf(float f) {
    unsigned u;
    asm("cvt.rna.tf32.f32 %0, %1;" : "=r"(u) : "f"(f));
    return u;
}

__device__ __forceinline__ void mma_tf32(float* c, const unsigned* a, const unsigned* b) {
    asm("mma.sync.aligned.m16n8k8.row.col.f32.tf32.tf32.f32 "
        "{%0,%1,%2,%3},{%4,%5,%6,%7},{%8,%9},{%0,%1,%2,%3};"
        : "+f"(c[0]), "+f"(c[1]), "+f"(c[2]), "+f"(c[3])
        : "r"(a[0]), "r"(a[1]), "r"(a[2]), "r"(a[3]), "r"(b[0]), "r"(b[1]));
}

// ---------------------------------------------------------------------------
// Projection GEMM: C = A[S,DM] @ W[N,DM]^T, tf32 tensor cores.
// CTA tile 128x128, Ktile 32, 8 warps in 2(m) x 4(n), warp tile 64x32.
// Software-pipelined: next K-tile is prefetched into registers while the
// current tile's MMAs consume smem (hides LDG latency behind tensor work).
// Smem [row][36] padding: stride%32==4 -> conflict-free fragment LDS.
// mode 0: A=A_ext (x), W per blockIdx.z, C = g_q/g_k/g_v head-major.
// mode 1: A=g_ao, W=W0 (Wo), C = C_ext (d_out) row-major [s][DM].
// ---------------------------------------------------------------------------
__global__ __launch_bounds__(256) void proj_gemm(
    const float* __restrict__ A_ext,
    const float* __restrict__ W0, const float* __restrict__ W1,
    const float* __restrict__ W2,
    float* __restrict__ C_ext, int mode)
{
    __shared__ unsigned As[128 * 36];
    __shared__ unsigned Bs[128 * 36];

    const float* A;
    const float* W;
    float* C;
    if (mode == 0) {
        A = A_ext;
        W = (blockIdx.z == 0) ? W0 : ((blockIdx.z == 1) ? W1 : W2);
        C = (blockIdx.z == 0) ? g_q : ((blockIdx.z == 1) ? g_k : g_v);
    } else {
        A = g_ao;
        W = W0;
        C = C_ext;
    }

    const int tid = threadIdx.x;
    const int wid = tid >> 5, lane = tid & 31;
    const int g = lane >> 2, q = lane & 3;
    const int wm = (wid >> 2) * 64;
    const int wn = (wid & 3) * 32;
    const int row0 = blockIdx.x << 7;
    const int col0 = blockIdx.y << 7;
    const int lr = tid >> 3;             // 0..31
    const int lc = (tid & 7) << 2;       // 0..28

    float acc[4][4][4];
#pragma unroll
    for (int i = 0; i < 4; i++)
#pragma unroll
        for (int j = 0; j < 4; j++)
#pragma unroll
            for (int r = 0; r < 4; r++) acc[i][j][r] = 0.f;

    // prologue: prefetch K-tile 0
    float4 apre[4], bpre[4];
#pragma unroll
    for (int c = 0; c < 4; c++) {
        int r = c * 32 + lr;
        apre[c] = *(const float4*)(A + (size_t)(row0 + r) * DM + lc);
        bpre[c] = *(const float4*)(W + (size_t)(col0 + r) * DM + lc);
    }

    for (int kt = 0; kt < DM; kt += 32) {
        // commit prefetched tile to smem (tf32)
#pragma unroll
        for (int c = 0; c < 4; c++) {
            int r = c * 32 + lr;
            *(uint4*)&As[r * 36 + lc] =
                make_uint4(f2tf(apre[c].x), f2tf(apre[c].y), f2tf(apre[c].z), f2tf(apre[c].w));
            *(uint4*)&Bs[r * 36 + lc] =
                make_uint4(f2tf(bpre[c].x), f2tf(bpre[c].y), f2tf(bpre[c].z), f2tf(bpre[c].w));
        }
        __syncthreads();

        // issue next tile's loads; latency hides behind the MMA section
        if (kt + 32 < DM) {
#pragma unroll
            for (int c = 0; c < 4; c++) {
                int r = c * 32 + lr;
                apre[c] = *(const float4*)(A + (size_t)(row0 + r) * DM + kt + 32 + lc);
                bpre[c] = *(const float4*)(W + (size_t)(col0 + r) * DM + kt + 32 + lc);
            }
        }

#pragma unroll
        for (int ks = 0; ks < 4; ks++) {
            unsigned af[4][4], bf[4][2];
#pragma unroll
            for (int mt = 0; mt < 4; mt++) {
                int base = (wm + mt * 16 + g) * 36 + ks * 8 + q;
                af[mt][0] = As[base];
                af[mt][1] = As[base + 8 * 36];
                af[mt][2] = As[base + 4];
                af[mt][3] = As[base + 8 * 36 + 4];
            }
#pragma unroll
            for (int nt = 0; nt < 4; nt++) {
                int base = (wn + nt * 8 + g) * 36 + ks * 8 + q;
                bf[nt][0] = Bs[base];
                bf[nt][1] = Bs[base + 4];
            }
#pragma unroll
            for (int mt = 0; mt < 4; mt++)
#pragma unroll
                for (int nt = 0; nt < 4; nt++)
                    mma_tf32(acc[mt][nt], af[mt], bf[nt]);
        }
        __syncthreads();
    }

#pragma unroll
    for (int mt = 0; mt < 4; mt++)
#pragma unroll
        for (int nt = 0; nt < 4; nt++) {
            int row = row0 + wm + mt * 16 + g;
            int col = col0 + wn + nt * 8 + 2 * q;
            if (mode == 0) {
                float* p0 = C + (size_t)(col >> 6) * SQ * HDIM + (size_t)row * HDIM + (col & 63);
                float* p1 = C + (size_t)(col >> 6) * SQ * HDIM + (size_t)(row + 8) * HDIM + (col & 63);
                p0[0] = acc[mt][nt][0]; p0[1] = acc[mt][nt][1];
                p1[0] = acc[mt][nt][2]; p1[1] = acc[mt][nt][3];
            } else {
                float* p0 = C + (size_t)row * DM + col;
                float* p1 = C + (size_t)(row + 8) * DM + col;
                p0[0] = acc[mt][nt][0]; p0[1] = acc[mt][nt][1];
                p1[0] = acc[mt][nt][2]; p1[1] = acc[mt][nt][3];
            }
        }
}

// ---------------------------------------------------------------------------
// Causal flash attention, tf32 tensor cores, software-pipelined K/V loads.
// 128 threads = 4 warps; warp owns 16 score rows x full 64 cols.
// Next jt's K/V tile is prefetched into registers during the current tile's
// mma/softmax work. Q fragments preloaded to registers (Q smem reused as P).
// Smem: Qs/Ps [64][68], Ks [64][68], Vt [64][72] (k-major V).
// ---------------------------------------------------------------------------
__global__ __launch_bounds__(128) void attn_kernel()
{
    extern __shared__ unsigned sm[];
    unsigned* Qs = sm;                   // [64][68], later reused as Ps
    unsigned* Ks = sm + 64 * 68;         // [64][68]
    unsigned* Vt = sm + 2 * 64 * 68;     // [64][72] : Vt[k*72 + hd]
    unsigned* Ps = Qs;

    const int tid = threadIdx.x;
    const int wid = tid >> 5, lane = tid & 31;
    const int g = lane >> 2, q = lane & 3;
    const int wm = wid * 16;
    const int qt = 63 - blockIdx.x;      // reversed: heavy tiles first
    const int h = blockIdx.y;
    const int lr = tid >> 4;             // 0..7
    const int lc = (tid & 15) << 2;      // 0..60

    const float* Qh = g_q + (size_t)h * SQ * HDIM;
    const float* Kh = g_k + (size_t)h * SQ * HDIM;
    const float* Vh = g_v + (size_t)h * SQ * HDIM;

    // Q tile -> smem (tf32)
#pragma unroll
    for (int c = 0; c < 8; c++) {
        int r = c * 8 + lr;
        float4 v = *(const float4*)(Qh + (size_t)(qt * 64 + r) * HDIM + lc);
        *(uint4*)&Qs[r * 68 + lc] = make_uint4(f2tf(v.x), f2tf(v.y), f2tf(v.z), f2tf(v.w));
    }
    __syncthreads();

    // Q fragments -> registers (invariant across jt); own-warp rows only
    unsigned qf[8][4];
#pragma unroll
    for (int ks = 0; ks < 8; ks++) {
        int base = (wm + g) * 68 + ks * 8 + q;
        qf[ks][0] = Qs[base];
        qf[ks][1] = Qs[base + 8 * 68];
        qf[ks][2] = Qs[base + 4];
        qf[ks][3] = Qs[base + 8 * 68 + 4];
    }

    float oacc[8][4];
#pragma unroll
    for (int nt = 0; nt < 8; nt++)
#pragma unroll
        for (int r = 0; r < 4; r++) oacc[nt][r] = 0.f;
    float m0 = -1e30f, m1 = -1e30f, l0 = 0.f, l1 = 0.f;
    const float scale = 0.125f;

    // prologue: prefetch jt=0 K/V tile into registers
    float4 kpre[8], vpre[8];
#pragma unroll
    for (int c = 0; c < 8; c++) {
        int r = c * 8 + lr;
        kpre[c] = *(const float4*)(Kh + (size_t)r * HDIM + lc);
        vpre[c] = *(const float4*)(Vh + (size_t)r * HDIM + lc);
    }

    for (int jt = 0; jt <= qt; jt++) {
        __syncthreads();  // all warps done with prev Ks/Vt (and Qs frags on jt=0)
        // commit prefetched K/V to smem (tf32)
#pragma unroll
        for (int c = 0; c < 8; c++) {
            int r = c * 8 + lr;
            *(uint4*)&Ks[r * 68 + lc] =
                make_uint4(f2tf(kpre[c].x), f2tf(kpre[c].y), f2tf(kpre[c].z), f2tf(kpre[c].w));
            *(uint4*)&Vt[r * 72 + lc] =
                make_uint4(f2tf(vpre[c].x), f2tf(vpre[c].y), f2tf(vpre[c].z), f2tf(vpre[c].w));
        }
        __syncthreads();

        // issue next tile's loads; latency hides behind mma + softmax below
        if (jt < qt) {
#pragma unroll
            for (int c = 0; c < 8; c++) {
                int r = (jt + 1) * 64 + c * 8 + lr;
                kpre[c] = *(const float4*)(Kh + (size_t)r * HDIM + lc);
                vpre[c] = *(const float4*)(Vh + (size_t)r * HDIM + lc);
            }
        }

        // S = Q @ K^T  (warp: 16 x 64)
        float sa[8][4];
#pragma unroll
        for (int nt = 0; nt < 8; nt++)
#pragma unroll
            for (int r = 0; r < 4; r++) sa[nt][r] = 0.f;
#pragma unroll
        for (int ks = 0; ks < 8; ks++) {
            unsigned kf[8][2];
#pragma unroll
            for (int nt = 0; nt < 8; nt++) {
                int base = (nt * 8 + g) * 68 + ks * 8 + q;
                kf[nt][0] = Ks[base];
                kf[nt][1] = Ks[base + 4];
            }
#pragma unroll
            for (int nt = 0; nt < 8; nt++)
                mma_tf32(sa[nt], qf[ks], kf[nt]);
        }

        // scale + causal mask (diag tile only)
        if (jt == qt) {
            int r0 = wm + g, r1 = wm + g + 8;
#pragma unroll
            for (int nt = 0; nt < 8; nt++) {
                int c0 = nt * 8 + 2 * q, c1 = c0 + 1;
                sa[nt][0] = (c0 > r0) ? -1e30f : sa[nt][0] * scale;
                sa[nt][1] = (c1 > r0) ? -1e30f : sa[nt][1] * scale;
                sa[nt][2] = (c0 > r1) ? -1e30f : sa[nt][2] * scale;
                sa[nt][3] = (c1 > r1) ? -1e30f : sa[nt][3] * scale;
            }
        } else {
#pragma unroll
            for (int nt = 0; nt < 8; nt++)
#pragma unroll
                for (int r = 0; r < 4; r++) sa[nt][r] *= scale;
        }

        // online softmax: rows r0 (c0,c1) and r1 (c2,c3); quad shuffles
        float rm0 = -1e30f, rm1 = -1e30f;
#pragma unroll
        for (int nt = 0; nt < 8; nt++) {
            rm0 = fmaxf(rm0, fmaxf(sa[nt][0], sa[nt][1]));
            rm1 = fmaxf(rm1, fmaxf(sa[nt][2], sa[nt][3]));
        }
#pragma unroll
        for (int off = 1; off < 4; off <<= 1) {
            rm0 = fmaxf(rm0, __shfl_xor_sync(0xffffffffu, rm0, off));
            rm1 = fmaxf(rm1, __shfl_xor_sync(0xffffffffu, rm1, off));
        }
        float mn0 = fmaxf(m0, rm0), mn1 = fmaxf(m1, rm1);
        float al0 = __expf(m0 - mn0), al1 = __expf(m1 - mn1);
        m0 = mn0; m1 = mn1;
        float rs0 = 0.f, rs1 = 0.f;
#pragma unroll
        for (int nt = 0; nt < 8; nt++) {
            sa[nt][0] = __expf(sa[nt][0] - mn0);
            sa[nt][1] = __expf(sa[nt][1] - mn0);
            sa[nt][2] = __expf(sa[nt][2] - mn1);
            sa[nt][3] = __expf(sa[nt][3] - mn1);
            rs0 += sa[nt][0] + sa[nt][1];
            rs1 += sa[nt][2] + sa[nt][3];
        }
#pragma unroll
        for (int off = 1; off < 4; off <<= 1) {
            rs0 += __shfl_xor_sync(0xffffffffu, rs0, off);
            rs1 += __shfl_xor_sync(0xffffffffu, rs1, off);
        }
        l0 = l0 * al0 + rs0;
        l1 = l1 * al1 + rs1;
#pragma unroll
        for (int nt = 0; nt < 8; nt++) {
            oacc[nt][0] *= al0; oacc[nt][1] *= al0;
            oacc[nt][2] *= al1; oacc[nt][3] *= al1;
        }

        // P -> smem (tf32), own-warp rows only
#pragma unroll
        for (int nt = 0; nt < 8; nt++) {
            int a0 = (wm + g) * 68 + nt * 8 + 2 * q;
            int a1 = (wm + g + 8) * 68 + nt * 8 + 2 * q;
            Ps[a0] = f2tf(sa[nt][0]); Ps[a0 + 1] = f2tf(sa[nt][1]);
            Ps[a1] = f2tf(sa[nt][2]); Ps[a1 + 1] = f2tf(sa[nt][3]);
        }
        __syncwarp();

        // O += P @ V  (warp: 16 x 64)
#pragma unroll
        for (int ks = 0; ks < 8; ks++) {
            unsigned pf[4];
            int base = (wm + g) * 68 + ks * 8 + q;
            pf[0] = Ps[base];
            pf[1] = Ps[base + 8 * 68];
            pf[2] = Ps[base + 4];
            pf[3] = Ps[base + 8 * 68 + 4];
#pragma unroll
            for (int nt = 0; nt < 8; nt++) {
                unsigned vb[2];
                int vbase = (ks * 8 + q) * 72 + nt * 8 + g;
                vb[0] = Vt[vbase];
                vb[1] = Vt[vbase + 4 * 72];
                mma_tf32(oacc[nt], pf, vb);
            }
        }
    }

    // epilogue: normalize, write [s][d] for the output projection
    float inv0 = 1.f / l0, inv1 = 1.f / l1;
#pragma unroll
    for (int nt = 0; nt < 8; nt++) {
        int row = qt * 64 + wm + g;
        int col = h * HDIM + nt * 8 + 2 * q;
        float* p0 = g_ao + (size_t)row * DM + col;
        float* p1 = g_ao + (size_t)(row + 8) * DM + col;
        p0[0] = oacc[nt][0] * inv0; p0[1] = oacc[nt][1] * inv0;
        p1[0] = oacc[nt][2] * inv1; p1[1] = oacc[nt][3] * inv1;
    }
}

// ---------------------------------------------------------------------------
// inputs: 0=x, 1=mask (ignored; causal structural), 2=Wq, 3=Wk, 4=Wv, 5=Wo
// ---------------------------------------------------------------------------
extern "C" void kernel_launch(void* const* d_in, const int* in_sizes, int n_in,
                              void* d_out, int out_size)
{
    const float* x  = (const float*)d_in[0];
    const float* Wq = (const float*)d_in[2];
    const float* Wk = (const float*)d_in[3];
    const float* Wv = (const float*)d_in[4];
    const float* Wo = (const float*)d_in[5];
    float* out = (float*)d_out;

    cudaFuncSetAttribute(attn_kernel,
                         cudaFuncAttributeMaxDynamicSharedMemorySize, 53248);

    dim3 gq(SQ / 128, DM / 128, 3);
    proj_gemm<<<gq, 256>>>(x, Wq, Wk, Wv, nullptr, 0);

    dim3 ga(SQ / 64, NH);
    attn_kernel<<<ga, 128, 53248>>>();

    dim3 go(SQ / 128, DM / 128, 1);
    proj_gemm<<<go, 256>>>(nullptr, Wo, nullptr, nullptr, out, 1);
}